// round 15
// baseline (speedup 1.0000x reference)
#include <cuda_runtime.h>
#include <cstdint>

// Problem constants
#define NNODES 8192
#define FDIM   1024
#define ODIM   1024
#define KDIM   2048   // 2*FDIM
#define NNB    10

#define KT8 (KDIM / 8)        // 256 k-tiles of 8

// GEMM tiling: CTA 128x256, 16 warps (4M x 4N), warp tile 32x64, BK=32, 3-stage
#define BM 128
#define BN 256
#define BK 32
#define NTHREADS 512
#define NSTAGE 3
#define NKT (KDIM / BK)       // 64

// Stage sizes (fragment-order, no padding needed)
#define SA_BYTES (BM * BK * 4)          // 16384
#define SB_BYTES (BK * BN * 4)          // 32768
#define OFF_B (NSTAGE * SA_BYTES)       // 49152
#define SMEM_BYTES (NSTAGE * (SA_BYTES + SB_BYTES))   // 147456

// Scratch in mma-fragment order:
// A_perm[mtile(512)][ktile(256)][lane(32)][4]  (64 MB)
//   j: 0=(r,cl) 1=(r+8,cl) 2=(r,cl+4) 3=(r+8,cl+4), lane = r*4+cl
__device__ float g_Aperm[(size_t)(NNODES / 16) * KT8 * 128];
// B_perm[ntile(128)][ktile(256)][lane(32)][2]  (8 MB)
//   j: 0=(k+cl, n+r) 1=(k+cl+4, n+r), lane = r*4+cl
__device__ float g_Bperm[(size_t)(ODIM / 8) * KT8 * 64];

// ---------------------------------------------------------------------------
// PTX helpers (base-target sm_80+ PTX only — no tcgen05 on this toolchain)
// ---------------------------------------------------------------------------
__device__ __forceinline__ uint32_t smem_u32(const void* p) {
    uint32_t a;
    asm("{ .reg .u64 t; cvta.to.shared.u64 t, %1; cvt.u32.u64 %0, t; }"
        : "=r"(a) : "l"(p));
    return a;
}
__device__ __forceinline__ float rna_tf32(float x) {
    uint32_t r;
    asm("cvt.rna.tf32.f32 %0, %1;" : "=r"(r) : "f"(x));
    return __uint_as_float(r);
}
__device__ __forceinline__ void cp16(uint32_t dst, const float* src) {
    asm volatile("cp.async.cg.shared.global [%0], [%1], 16;"
                 :: "r"(dst), "l"(src) : "memory");
}
__device__ __forceinline__ void mma_tf32_16x8x8(float* d, const float4 a,
                                                const float2 b) {
    asm volatile(
        "mma.sync.aligned.m16n8k8.row.col.f32.tf32.tf32.f32 "
        "{%0,%1,%2,%3}, {%4,%5,%6,%7}, {%8,%9}, {%0,%1,%2,%3};"
        : "+f"(d[0]), "+f"(d[1]), "+f"(d[2]), "+f"(d[3])
        : "r"(__float_as_uint(a.x)), "r"(__float_as_uint(a.y)),
          "r"(__float_as_uint(a.z)), "r"(__float_as_uint(a.w)),
          "r"(__float_as_uint(b.x)), "r"(__float_as_uint(b.y)));
}

// Staging swizzle: XOR float-addr bits [2:4] with ktile bits — float4-safe.
__device__ __forceinline__ int swz(int a) {
    return a ^ (((a >> 7) & 7) << 2);
}

// ---------------------------------------------------------------------------
// Prep A v3 (unchanged, measured 33us): block per (mtile, 512-k chunk).
// ---------------------------------------------------------------------------
__global__ void __launch_bounds__(256) prepA_kernel(const float* __restrict__ X,
                                                    const int* __restrict__ idx) {
    __shared__ float stage[8192];   // 32 KB: 16 rows x 512 k, fragment order
    const int mt   = blockIdx.x >> 2;
    const int c    = blockIdx.x & 3;
    const int k0   = c * 512;
    const int t    = threadIdx.x;
    const int wid  = t >> 5;        // = r (0..7)
    const int lane = t & 31;
    const float4* Xv = reinterpret_cast<const float4*>(X);

#pragma unroll
    for (int rr = 0; rr < 2; ++rr) {
        const int m = mt * 16 + wid + rr * 8;

        if (c < 2) {
#pragma unroll
            for (int it = 0; it < 4; ++it) {
                const int kidx = it * 32 + lane;   // float4 index in chunk
                float4 v = __ldg(Xv + (size_t)m * (FDIM / 4) + (k0 >> 2) + kidx);
                v.x = rna_tf32(v.x); v.y = rna_tf32(v.y);
                v.z = rna_tf32(v.z); v.w = rna_tf32(v.w);
                const int ktl = kidx >> 1, khalf = kidx & 1;
                const int a0 = ktl * 128 + khalf * 2 + rr;
                stage[swz(a0 + (wid * 4 + 0) * 4)] = v.x;
                stage[swz(a0 + (wid * 4 + 1) * 4)] = v.y;
                stage[swz(a0 + (wid * 4 + 2) * 4)] = v.z;
                stage[swz(a0 + (wid * 4 + 3) * 4)] = v.w;
            }
        } else {
            int nb[NNB];
#pragma unroll
            for (int j = 0; j < NNB; ++j) nb[j] = __ldg(idx + m * NNB + j);
#pragma unroll
            for (int it = 0; it < 4; ++it) {
                const int kidx = it * 32 + lane;
                const int kq = ((k0 - FDIM) >> 2) + kidx;
                float4 acc = make_float4(0.f, 0.f, 0.f, 0.f);
#pragma unroll
                for (int j = 0; j < NNB; ++j) {
                    const float4 w = __ldg(Xv + (size_t)nb[j] * (FDIM / 4) + kq);
                    acc.x += w.x; acc.y += w.y; acc.z += w.z; acc.w += w.w;
                }
                const float s = 1.0f / (float)NNB;
                float4 v;
                v.x = rna_tf32(acc.x * s); v.y = rna_tf32(acc.y * s);
                v.z = rna_tf32(acc.z * s); v.w = rna_tf32(acc.w * s);
                const int ktl = kidx >> 1, khalf = kidx & 1;
                const int a0 = ktl * 128 + khalf * 2 + rr;
                stage[swz(a0 + (wid * 4 + 0) * 4)] = v.x;
                stage[swz(a0 + (wid * 4 + 1) * 4)] = v.y;
                stage[swz(a0 + (wid * 4 + 2) * 4)] = v.z;
                stage[swz(a0 + (wid * 4 + 3) * 4)] = v.w;
            }
        }
    }
    __syncthreads();

    float* gdst = g_Aperm + ((size_t)mt * KT8 + c * 64) * 128;
#pragma unroll
    for (int i = 0; i < 8; ++i) {
        const int o = (t + i * 256) * 4;
        const float4 val = *reinterpret_cast<const float4*>(&stage[swz(o)]);
        *reinterpret_cast<float4*>(gdst + o) = val;
    }
}

// ---------------------------------------------------------------------------
// Prep B v2 (unchanged): block = (ntile, k-half).
// ---------------------------------------------------------------------------
__global__ void __launch_bounds__(256) prepB_kernel(const float* __restrict__ W) {
    __shared__ float stage[8192];   // 32 KB
    const int nt  = blockIdx.x >> 1;
    const int kc0 = (blockIdx.x & 1) * 1024;
    const int t   = threadIdx.x;
    const int nl  = t & 7;           // n_local = r
    const int kb  = t >> 3;          // 0..31

#pragma unroll
    for (int i = 0; i < 32; ++i) {
        const int k = kc0 + kb + i * 32;
        const float v = rna_tf32(__ldg(W + (size_t)k * ODIM + nt * 8 + nl));
        const int kl = k - kc0;
        const int ktl = kl >> 3, cl = k & 3, khalf = (k >> 2) & 1;
        stage[ktl * 64 + (nl * 4 + cl) * 2 + khalf] = v;
    }
    __syncthreads();

    float* gdst = g_Bperm + ((size_t)nt * KT8 + (kc0 >> 3)) * 64;
#pragma unroll
    for (int i = 0; i < 8; ++i) {
        const int o = (t + i * 256) * 4;
        *reinterpret_cast<float4*>(gdst + o) =
            *reinterpret_cast<const float4*>(&stage[o]);
    }
}

// ---------------------------------------------------------------------------
// Main GEMM v2: 512 threads, 16 warps (4M x 4N), warp tile 32x64.
// 4 warps/SMSP for latency hiding; single-buffer fragments (~100 regs).
// ---------------------------------------------------------------------------
__device__ __forceinline__ void load_stage(uint32_t sA, uint32_t sB,
                                           const float* __restrict__ gA,
                                           const float* __restrict__ gB,
                                           int kt, int tid) {
    const int kt4 = kt * 4;
    // A: 1024 chunks of 16B, 2 per thread
#pragma unroll
    for (int i = 0; i < 2; ++i) {
        const int c = tid + i * NTHREADS;
        const int t32 = c >> 5, off = (c & 31) * 4;
        const int mt = t32 >> 2, k4 = t32 & 3;
        cp16(sA + (uint32_t)c * 16,
             gA + ((size_t)mt * KT8 + kt4 + k4) * 128 + off);
    }
    // B: 2048 chunks of 16B, 4 per thread
#pragma unroll
    for (int i = 0; i < 4; ++i) {
        const int c = tid + i * NTHREADS;
        const int t16 = c >> 4, off = (c & 15) * 4;
        const int nt = t16 >> 2, k4 = t16 & 3;
        cp16(sB + (uint32_t)c * 16,
             gB + ((size_t)nt * KT8 + kt4 + k4) * 64 + off);
    }
}

__global__ void __launch_bounds__(NTHREADS, 1) gemm_mma_kernel(
    const float* __restrict__ bias, float* __restrict__ out) {
    extern __shared__ float smem[];
    const uint32_t smem_b = smem_u32(smem);

    const int tid = threadIdx.x;
    const int wid = tid >> 5, lane = tid & 31;
    const int wm = wid & 3;          // warp M index (0..3) -> 32 rows
    const int wn = wid >> 2;         // warp N index (0..3) -> 64 cols
    const int m0 = blockIdx.y * BM;
    const int n0 = blockIdx.x * BN;

    const float* gA = g_Aperm + (size_t)(m0 >> 4) * KT8 * 128;
    const float* gB = g_Bperm + (size_t)(n0 >> 3) * KT8 * 64;

    const int r  = lane >> 2;
    const int cl = lane & 3;

    float acc[2][8][4];
#pragma unroll
    for (int mt = 0; mt < 2; ++mt)
#pragma unroll
        for (int nt = 0; nt < 8; ++nt)
#pragma unroll
            for (int i = 0; i < 4; ++i) acc[mt][nt][i] = 0.f;

    load_stage(smem_b, smem_b + OFF_B, gA, gB, 0, tid);
    asm volatile("cp.async.commit_group;" ::: "memory");
    load_stage(smem_b + SA_BYTES, smem_b + OFF_B + SB_BYTES, gA, gB, 1, tid);
    asm volatile("cp.async.commit_group;" ::: "memory");

    for (int kt = 0; kt < NKT; ++kt) {
        asm volatile("cp.async.wait_group 1;" ::: "memory");
        __syncthreads();

        const int ls = kt + 2;
        if (ls < NKT) {
            const int b = ls % NSTAGE;
            load_stage(smem_b + b * SA_BYTES, smem_b + OFF_B + b * SB_BYTES,
                       gA, gB, ls, tid);
        }
        asm volatile("cp.async.commit_group;" ::: "memory");

        const int b = kt % NSTAGE;
        // Warp bases: A mtile = wm*2 + mt, layout [mtile][k4][128]
        const float* As = smem + (b * SA_BYTES) / 4
                        + (wm * 2) * 4 * 128 + lane * 4;
        // B ntile = wn*8 + nt, layout [ntile][k4][64]
        const float* Bs = smem + (OFF_B + b * SB_BYTES) / 4
                        + (wn * 8) * 4 * 64 + lane * 2;

#pragma unroll
        for (int ks = 0; ks < 4; ++ks) {
            float4 af[2];
            float2 bf[8];
#pragma unroll
            for (int mt = 0; mt < 2; ++mt)
                af[mt] = *reinterpret_cast<const float4*>(
                    As + (mt * 4 + ks) * 128);
#pragma unroll
            for (int nt = 0; nt < 8; ++nt)
                bf[nt] = *reinterpret_cast<const float2*>(
                    Bs + (nt * 4 + ks) * 64);
#pragma unroll
            for (int mt = 0; mt < 2; ++mt)
#pragma unroll
                for (int nt = 0; nt < 8; ++nt)
                    mma_tf32_16x8x8(acc[mt][nt], af[mt], bf[nt]);
        }
    }

    // Epilogue
#pragma unroll
    for (int nt = 0; nt < 8; ++nt) {
        const int col = n0 + wn * 64 + nt * 8 + cl * 2;
        const float2 bv = __ldg(reinterpret_cast<const float2*>(bias + col));
#pragma unroll
        for (int mt = 0; mt < 2; ++mt) {
            const int row = m0 + wm * 32 + mt * 16 + r;
            float2 o0, o1;
            o0.x = acc[mt][nt][0] + bv.x;
            o0.y = acc[mt][nt][1] + bv.y;
            o1.x = acc[mt][nt][2] + bv.x;
            o1.y = acc[mt][nt][3] + bv.y;
            *reinterpret_cast<float2*>(out + (size_t)row * ODIM + col) = o0;
            *reinterpret_cast<float2*>(out + (size_t)(row + 8) * ODIM + col) = o1;
        }
    }
}

// ---------------------------------------------------------------------------
// Launch: inputs per metadata order: X, A (dead), W, b, sampled_idx
// ---------------------------------------------------------------------------
extern "C" void kernel_launch(void* const* d_in, const int* in_sizes, int n_in,
                              void* d_out, int out_size) {
    const float* X    = (const float*)d_in[0];
    // d_in[1] = dense adjacency A, dead input (never influences output)
    const float* W    = (const float*)d_in[2];
    const float* bias = (const float*)d_in[3];
    const int*   idx  = (const int*)d_in[4];
    float*       out  = (float*)d_out;

    cudaFuncSetAttribute(gemm_mma_kernel,
                         cudaFuncAttributeMaxDynamicSharedMemorySize, SMEM_BYTES);

    prepA_kernel<<<(NNODES / 16) * 4, 256>>>(X, idx);
    prepB_kernel<<<256, 256>>>(W);

    dim3 grid(ODIM / BN, NNODES / BM);   // (4, 64) = 256 CTAs
    gemm_mma_kernel<<<grid, NTHREADS, SMEM_BYTES>>>(bias, out);
}

// round 17
// speedup vs baseline: 1.1293x; 1.1293x over previous
#include <cuda_runtime.h>
#include <cstdint>

// Problem constants
#define NNODES 8192
#define FDIM   1024
#define ODIM   1024
#define KDIM   2048   // 2*FDIM
#define NNB    10

#define KT8 (KDIM / 8)        // 256 k-tiles of 8

// GEMM tiling: CTA 128x128, 4 warps (2M x 2N), warp tile 64x64, BK=32,
// 3-stage, 96KB smem -> 2 CTAs/SM (decoupled barriers).
#define BM 128
#define BN 128
#define BK 32
#define NTHREADS 128
#define NSTAGE 3
#define NKT (KDIM / BK)       // 64

#define SA_BYTES (BM * BK * 4)          // 16384
#define SB_BYTES (BK * BN * 4)          // 16384
#define OFF_B (NSTAGE * SA_BYTES)       // 49152
#define SMEM_BYTES (NSTAGE * (SA_BYTES + SB_BYTES))   // 98304

// Scratch in mma-fragment order:
// A_perm[mtile(512)][ktile(256)][lane(32)][4]  (64 MB)
__device__ float g_Aperm[(size_t)(NNODES / 16) * KT8 * 128];
// B_perm[ntile(128)][ktile(256)][lane(32)][2]  (8 MB)
__device__ float g_Bperm[(size_t)(ODIM / 8) * KT8 * 64];

// ---------------------------------------------------------------------------
// PTX helpers (base-target sm_80+ PTX only — no tcgen05 on this toolchain)
// ---------------------------------------------------------------------------
__device__ __forceinline__ uint32_t smem_u32(const void* p) {
    uint32_t a;
    asm("{ .reg .u64 t; cvta.to.shared.u64 t, %1; cvt.u32.u64 %0, t; }"
        : "=r"(a) : "l"(p));
    return a;
}
__device__ __forceinline__ float rna_tf32(float x) {
    uint32_t r;
    asm("cvt.rna.tf32.f32 %0, %1;" : "=r"(r) : "f"(x));
    return __uint_as_float(r);
}
__device__ __forceinline__ void cp16(uint32_t dst, const float* src) {
    asm volatile("cp.async.cg.shared.global [%0], [%1], 16;"
                 :: "r"(dst), "l"(src) : "memory");
}
__device__ __forceinline__ void mma_tf32_16x8x8(float* d, const float4 a,
                                                const float2 b) {
    asm volatile(
        "mma.sync.aligned.m16n8k8.row.col.f32.tf32.tf32.f32 "
        "{%0,%1,%2,%3}, {%4,%5,%6,%7}, {%8,%9}, {%0,%1,%2,%3};"
        : "+f"(d[0]), "+f"(d[1]), "+f"(d[2]), "+f"(d[3])
        : "r"(__float_as_uint(a.x)), "r"(__float_as_uint(a.y)),
          "r"(__float_as_uint(a.z)), "r"(__float_as_uint(a.w)),
          "r"(__float_as_uint(b.x)), "r"(__float_as_uint(b.y)));
}

// Staging swizzle: XOR float-addr bits [2:4] with ktile bits — float4-safe.
__device__ __forceinline__ int swz(int a) {
    return a ^ (((a >> 7) & 7) << 2);
}

// ---------------------------------------------------------------------------
// Prep A v3 (unchanged, measured 33us): block per (mtile, 512-k chunk).
// ---------------------------------------------------------------------------
__global__ void __launch_bounds__(256) prepA_kernel(const float* __restrict__ X,
                                                    const int* __restrict__ idx) {
    __shared__ float stage[8192];   // 32 KB: 16 rows x 512 k, fragment order
    const int mt   = blockIdx.x >> 2;
    const int c    = blockIdx.x & 3;
    const int k0   = c * 512;
    const int t    = threadIdx.x;
    const int wid  = t >> 5;        // = r (0..7)
    const int lane = t & 31;
    const float4* Xv = reinterpret_cast<const float4*>(X);

#pragma unroll
    for (int rr = 0; rr < 2; ++rr) {
        const int m = mt * 16 + wid + rr * 8;

        if (c < 2) {
#pragma unroll
            for (int it = 0; it < 4; ++it) {
                const int kidx = it * 32 + lane;   // float4 index in chunk
                float4 v = __ldg(Xv + (size_t)m * (FDIM / 4) + (k0 >> 2) + kidx);
                v.x = rna_tf32(v.x); v.y = rna_tf32(v.y);
                v.z = rna_tf32(v.z); v.w = rna_tf32(v.w);
                const int ktl = kidx >> 1, khalf = kidx & 1;
                const int a0 = ktl * 128 + khalf * 2 + rr;
                stage[swz(a0 + (wid * 4 + 0) * 4)] = v.x;
                stage[swz(a0 + (wid * 4 + 1) * 4)] = v.y;
                stage[swz(a0 + (wid * 4 + 2) * 4)] = v.z;
                stage[swz(a0 + (wid * 4 + 3) * 4)] = v.w;
            }
        } else {
            int nb[NNB];
#pragma unroll
            for (int j = 0; j < NNB; ++j) nb[j] = __ldg(idx + m * NNB + j);
#pragma unroll
            for (int it = 0; it < 4; ++it) {
                const int kidx = it * 32 + lane;
                const int kq = ((k0 - FDIM) >> 2) + kidx;
                float4 acc = make_float4(0.f, 0.f, 0.f, 0.f);
#pragma unroll
                for (int j = 0; j < NNB; ++j) {
                    const float4 w = __ldg(Xv + (size_t)nb[j] * (FDIM / 4) + kq);
                    acc.x += w.x; acc.y += w.y; acc.z += w.z; acc.w += w.w;
                }
                const float s = 1.0f / (float)NNB;
                float4 v;
                v.x = rna_tf32(acc.x * s); v.y = rna_tf32(acc.y * s);
                v.z = rna_tf32(acc.z * s); v.w = rna_tf32(acc.w * s);
                const int ktl = kidx >> 1, khalf = kidx & 1;
                const int a0 = ktl * 128 + khalf * 2 + rr;
                stage[swz(a0 + (wid * 4 + 0) * 4)] = v.x;
                stage[swz(a0 + (wid * 4 + 1) * 4)] = v.y;
                stage[swz(a0 + (wid * 4 + 2) * 4)] = v.z;
                stage[swz(a0 + (wid * 4 + 3) * 4)] = v.w;
            }
        }
    }
    __syncthreads();

    float* gdst = g_Aperm + ((size_t)mt * KT8 + c * 64) * 128;
#pragma unroll
    for (int i = 0; i < 8; ++i) {
        const int o = (t + i * 256) * 4;
        const float4 val = *reinterpret_cast<const float4*>(&stage[swz(o)]);
        *reinterpret_cast<float4*>(gdst + o) = val;
    }
}

// ---------------------------------------------------------------------------
// Prep B v2 (unchanged): block = (ntile, k-half).
// ---------------------------------------------------------------------------
__global__ void __launch_bounds__(256) prepB_kernel(const float* __restrict__ W) {
    __shared__ float stage[8192];   // 32 KB
    const int nt  = blockIdx.x >> 1;
    const int kc0 = (blockIdx.x & 1) * 1024;
    const int t   = threadIdx.x;
    const int nl  = t & 7;           // n_local = r
    const int kb  = t >> 3;          // 0..31

#pragma unroll
    for (int i = 0; i < 32; ++i) {
        const int k = kc0 + kb + i * 32;
        const float v = rna_tf32(__ldg(W + (size_t)k * ODIM + nt * 8 + nl));
        const int kl = k - kc0;
        const int ktl = kl >> 3, cl = k & 3, khalf = (k >> 2) & 1;
        stage[ktl * 64 + (nl * 4 + cl) * 2 + khalf] = v;
    }
    __syncthreads();

    float* gdst = g_Bperm + ((size_t)nt * KT8 + (kc0 >> 3)) * 64;
#pragma unroll
    for (int i = 0; i < 8; ++i) {
        const int o = (t + i * 256) * 4;
        *reinterpret_cast<float4*>(gdst + o) =
            *reinterpret_cast<const float4*>(&stage[o]);
    }
}

// ---------------------------------------------------------------------------
// Main GEMM v3: CTA 128x128, 128 threads, 4 warps (2M x 2N), warp tile 64x64.
// 96KB smem -> 2 CTAs/SM; independent barriers hide each other's kt stalls.
// ---------------------------------------------------------------------------
__device__ __forceinline__ void load_stage(uint32_t sA, uint32_t sB,
                                           const float* __restrict__ gA,
                                           const float* __restrict__ gB,
                                           int kt, int tid) {
    const int kt4 = kt * 4;
    // A: 1024 chunks of 16B, 8 per thread
#pragma unroll
    for (int i = 0; i < 8; ++i) {
        const int c = tid + i * NTHREADS;
        const int t32 = c >> 5, off = (c & 31) * 4;
        const int mt = t32 >> 2, k4 = t32 & 3;
        cp16(sA + (uint32_t)c * 16,
             gA + ((size_t)mt * KT8 + kt4 + k4) * 128 + off);
    }
    // B: 1024 chunks of 16B, 8 per thread
#pragma unroll
    for (int i = 0; i < 8; ++i) {
        const int c = tid + i * NTHREADS;
        const int t16 = c >> 4, off = (c & 15) * 4;
        const int nt = t16 >> 2, k4 = t16 & 3;
        cp16(sB + (uint32_t)c * 16,
             gB + ((size_t)nt * KT8 + kt4 + k4) * 64 + off);
    }
}

__global__ void __launch_bounds__(NTHREADS, 2) gemm_mma_kernel(
    const float* __restrict__ bias, float* __restrict__ out) {
    extern __shared__ float smem[];
    const uint32_t smem_b = smem_u32(smem);

    const int tid = threadIdx.x;
    const int wid = tid >> 5, lane = tid & 31;
    const int wm = wid & 1;          // warp M index (0..1) -> 64 rows
    const int wn = wid >> 1;         // warp N index (0..1) -> 64 cols
    const int m0 = blockIdx.y * BM;
    const int n0 = blockIdx.x * BN;

    const float* gA = g_Aperm + (size_t)(m0 >> 4) * KT8 * 128;
    const float* gB = g_Bperm + (size_t)(n0 >> 3) * KT8 * 64;

    const int r  = lane >> 2;
    const int cl = lane & 3;

    float acc[4][8][4];
#pragma unroll
    for (int mt = 0; mt < 4; ++mt)
#pragma unroll
        for (int nt = 0; nt < 8; ++nt)
#pragma unroll
            for (int i = 0; i < 4; ++i) acc[mt][nt][i] = 0.f;

    load_stage(smem_b, smem_b + OFF_B, gA, gB, 0, tid);
    asm volatile("cp.async.commit_group;" ::: "memory");
    load_stage(smem_b + SA_BYTES, smem_b + OFF_B + SB_BYTES, gA, gB, 1, tid);
    asm volatile("cp.async.commit_group;" ::: "memory");

    for (int kt = 0; kt < NKT; ++kt) {
        asm volatile("cp.async.wait_group 1;" ::: "memory");
        __syncthreads();

        const int ls = kt + 2;
        if (ls < NKT) {
            const int b = ls % NSTAGE;
            load_stage(smem_b + b * SA_BYTES, smem_b + OFF_B + b * SB_BYTES,
                       gA, gB, ls, tid);
        }
        asm volatile("cp.async.commit_group;" ::: "memory");

        const int b = kt % NSTAGE;
        // Warp bases: A mtile = wm*4 + mt, layout [mtile][k4][128]
        const float* As = smem + (b * SA_BYTES) / 4
                        + (wm * 4) * 4 * 128 + lane * 4;
        // B ntile = wn*8 + nt, layout [ntile][k4][64]
        const float* Bs = smem + (OFF_B + b * SB_BYTES) / 4
                        + (wn * 8) * 4 * 64 + lane * 2;

        float4 af[2][4];
        float2 bf[2][8];

#pragma unroll
        for (int mt = 0; mt < 4; ++mt)
            af[0][mt] = *reinterpret_cast<const float4*>(As + mt * 4 * 128);
#pragma unroll
        for (int nt = 0; nt < 8; ++nt)
            bf[0][nt] = *reinterpret_cast<const float2*>(Bs + nt * 4 * 64);

#pragma unroll
        for (int ks = 0; ks < 4; ++ks) {
            const int cur = ks & 1, nxt = cur ^ 1;
            if (ks < 3) {
#pragma unroll
                for (int mt = 0; mt < 4; ++mt)
                    af[nxt][mt] = *reinterpret_cast<const float4*>(
                        As + (mt * 4 + ks + 1) * 128);
#pragma unroll
                for (int nt = 0; nt < 8; ++nt)
                    bf[nxt][nt] = *reinterpret_cast<const float2*>(
                        Bs + (nt * 4 + ks + 1) * 64);
            }
#pragma unroll
            for (int mt = 0; mt < 4; ++mt)
#pragma unroll
                for (int nt = 0; nt < 8; ++nt)
                    mma_tf32_16x8x8(acc[mt][nt], af[cur][mt], bf[cur][nt]);
        }
    }

    // Epilogue
#pragma unroll
    for (int nt = 0; nt < 8; ++nt) {
        const int col = n0 + wn * 64 + nt * 8 + cl * 2;
        const float2 bv = __ldg(reinterpret_cast<const float2*>(bias + col));
#pragma unroll
        for (int mt = 0; mt < 4; ++mt) {
            const int row = m0 + wm * 64 + mt * 16 + r;
            float2 o0, o1;
            o0.x = acc[mt][nt][0] + bv.x;
            o0.y = acc[mt][nt][1] + bv.y;
            o1.x = acc[mt][nt][2] + bv.x;
            o1.y = acc[mt][nt][3] + bv.y;
            *reinterpret_cast<float2*>(out + (size_t)row * ODIM + col) = o0;
            *reinterpret_cast<float2*>(out + (size_t)(row + 8) * ODIM + col) = o1;
        }
    }
}

// ---------------------------------------------------------------------------
// Launch: inputs per metadata order: X, A (dead), W, b, sampled_idx
// ---------------------------------------------------------------------------
extern "C" void kernel_launch(void* const* d_in, const int* in_sizes, int n_in,
                              void* d_out, int out_size) {
    const float* X    = (const float*)d_in[0];
    // d_in[1] = dense adjacency A, dead input (never influences output)
    const float* W    = (const float*)d_in[2];
    const float* bias = (const float*)d_in[3];
    const int*   idx  = (const int*)d_in[4];
    float*       out  = (float*)d_out;

    cudaFuncSetAttribute(gemm_mma_kernel,
                         cudaFuncAttributeMaxDynamicSharedMemorySize, SMEM_BYTES);

    prepA_kernel<<<(NNODES / 16) * 4, 256>>>(X, idx);
    prepB_kernel<<<256, 256>>>(W);

    dim3 grid(ODIM / BN, NNODES / BM);   // (8, 64) = 512 CTAs, 2/SM
    gemm_mma_kernel<<<grid, NTHREADS, SMEM_BYTES>>>(bias, out);
}